// round 2
// baseline (speedup 1.0000x reference)
#include <cuda_runtime.h>

#define T_DIM 2048
#define H_DIM 2048
#define NHEAD 16
#define HDIM 128
#define QKV_N (3 * H_DIM)
#define EPS_V 1e-6f
#define SCALE_V 0.08838834764831845f   // 128^-0.5
#define LOG_THETA 13.122363377404328f  // ln(500000)

// Scratch (device globals — no runtime allocation allowed)
__device__ float g_qkv[(size_t)T_DIM * QKV_N];   // 48 MB: [q | k | v] per row
__device__ float g_attn[(size_t)T_DIM * H_DIM];  // 16 MB

// ---------------------------------------------------------------------------
// Register-tiled SGEMM: C[M,N] = A[M,K] @ B[K,N], all row-major.
// 64x64 block tile, BK=16, 256 threads, 4x4 per thread.
// Requires M%64==0, N%64==0, K%16==0 (true for all shapes here).
// ---------------------------------------------------------------------------
__global__ void sgemm64(const float* __restrict__ A, const float* __restrict__ B,
                        float* __restrict__ C, int M, int N, int K) {
    __shared__ float As[16][65];  // padded: avoid bank conflicts on transposed store
    __shared__ float Bs[16][64];

    const int tx = threadIdx.x, ty = threadIdx.y;
    const int tid = ty * 16 + tx;
    const int row0 = blockIdx.y * 64;
    const int col0 = blockIdx.x * 64;

    float acc[4][4];
#pragma unroll
    for (int i = 0; i < 4; i++)
#pragma unroll
        for (int j = 0; j < 4; j++) acc[i][j] = 0.0f;

    for (int k0 = 0; k0 < K; k0 += 16) {
        // Load A tile (64 rows x 16 k): consecutive tids read contiguous k.
#pragma unroll
        for (int i = 0; i < 4; i++) {
            int e = tid + i * 256;
            int m = e >> 4, kk = e & 15;
            As[kk][m] = A[(size_t)(row0 + m) * K + k0 + kk];
        }
        // Load B tile (16 k x 64 cols): fully coalesced.
#pragma unroll
        for (int i = 0; i < 4; i++) {
            int e = tid + i * 256;
            int kk = e >> 6, n = e & 63;
            Bs[kk][n] = B[(size_t)(k0 + kk) * N + col0 + n];
        }
        __syncthreads();

#pragma unroll
        for (int kk = 0; kk < 16; kk++) {
            float a[4], b[4];
#pragma unroll
            for (int i = 0; i < 4; i++) a[i] = As[kk][ty * 4 + i];
#pragma unroll
            for (int j = 0; j < 4; j++) b[j] = Bs[kk][tx * 4 + j];
#pragma unroll
            for (int i = 0; i < 4; i++)
#pragma unroll
                for (int j = 0; j < 4; j++) acc[i][j] += a[i] * b[j];
        }
        __syncthreads();
    }

#pragma unroll
    for (int i = 0; i < 4; i++) {
        size_t r = (size_t)(row0 + ty * 4 + i) * N + col0 + tx * 4;
#pragma unroll
        for (int j = 0; j < 4; j++) C[r + j] = acc[i][j];
    }
}

// ---------------------------------------------------------------------------
// Fused RMSNorm (over full H=2048 for q and k) + RoPE, in-place on g_qkv.
// One block per token row, 256 threads.
// ---------------------------------------------------------------------------
__global__ void rmsnorm_rope_kernel(const int* __restrict__ positions,
                                    const float* __restrict__ qw,
                                    const float* __restrict__ kw) {
    const int t = blockIdx.x;
    float* q = g_qkv + (size_t)t * QKV_N;
    float* k = q + H_DIM;

    __shared__ float sh[32];
    const int lane = threadIdx.x & 31, warp = threadIdx.x >> 5;

    float sq = 0.0f, sk = 0.0f;
    for (int i = threadIdx.x; i < H_DIM; i += 256) {
        float a = q[i]; sq += a * a;
        float b = k[i]; sk += b * b;
    }
    // reduce sq
#pragma unroll
    for (int o = 16; o; o >>= 1) sq += __shfl_xor_sync(~0u, sq, o);
    if (lane == 0) sh[warp] = sq;
    __syncthreads();
    if (threadIdx.x < 32) {
        float v = (threadIdx.x < 8) ? sh[threadIdx.x] : 0.0f;
#pragma unroll
        for (int o = 4; o; o >>= 1) v += __shfl_xor_sync(~0u, v, o);
        if (threadIdx.x == 0) sh[0] = v;
    }
    __syncthreads();
    const float invq = rsqrtf(sh[0] / (float)H_DIM + EPS_V);
    __syncthreads();
    // reduce sk
#pragma unroll
    for (int o = 16; o; o >>= 1) sk += __shfl_xor_sync(~0u, sk, o);
    if (lane == 0) sh[warp] = sk;
    __syncthreads();
    if (threadIdx.x < 32) {
        float v = (threadIdx.x < 8) ? sh[threadIdx.x] : 0.0f;
#pragma unroll
        for (int o = 4; o; o >>= 1) v += __shfl_xor_sync(~0u, v, o);
        if (threadIdx.x == 0) sh[0] = v;
    }
    __syncthreads();
    const float invk = rsqrtf(sh[0] / (float)H_DIM + EPS_V);
    __syncthreads();

    const float p = (float)positions[t];
    // NHEAD * 64 = 1024 rotation pairs
    for (int idx = threadIdx.x; idx < NHEAD * (HDIM / 2); idx += 256) {
        const int h = idx >> 6;
        const int d = idx & 63;
        const int i1 = h * HDIM + d;
        const int i2 = i1 + (HDIM / 2);
        const float fr = p * __expf(-LOG_THETA * (float)d * (1.0f / 64.0f));
        float c, s;
        __sincosf(fr, &s, &c);

        float q1 = q[i1] * invq * qw[i1];
        float q2 = q[i2] * invq * qw[i2];
        q[i1] = q1 * c - q2 * s;
        q[i2] = q2 * c + q1 * s;

        float k1 = k[i1] * invk * kw[i1];
        float k2 = k[i2] * invk * kw[i2];
        k[i1] = k1 * c - k2 * s;
        k[i2] = k2 * c + k1 * s;
    }
}

// ---------------------------------------------------------------------------
// Causal attention: one block per (q-row, head). 128 threads.
// Scores in smem (<= 2048 floats), two-pass softmax, then PV.
// ---------------------------------------------------------------------------
__global__ void attn_kernel() {
    const int t = blockIdx.x;
    const int h = blockIdx.y;
    const int tid = threadIdx.x;
    const int lane = tid & 31, warp = tid >> 5;

    __shared__ float qs[HDIM];
    __shared__ float sc[T_DIM];
    __shared__ float red[32];

    const float* qrow = g_qkv + (size_t)t * QKV_N + h * HDIM;
    qs[tid] = qrow[tid] * SCALE_V;
    __syncthreads();

    const int nk = t + 1;

    // scores: each warp owns keys warp, warp+4, ...
    for (int kk = warp; kk < nk; kk += 4) {
        const float* krow = g_qkv + (size_t)kk * QKV_N + H_DIM + h * HDIM;
        float s = 0.0f;
#pragma unroll
        for (int d = lane; d < HDIM; d += 32) s += qs[d] * krow[d];
#pragma unroll
        for (int o = 16; o; o >>= 1) s += __shfl_xor_sync(~0u, s, o);
        if (lane == 0) sc[kk] = s;
    }
    __syncthreads();

    // max
    float m = -1e30f;
    for (int i = tid; i < nk; i += 128) m = fmaxf(m, sc[i]);
#pragma unroll
    for (int o = 16; o; o >>= 1) m = fmaxf(m, __shfl_xor_sync(~0u, m, o));
    if (lane == 0) red[warp] = m;
    __syncthreads();
    if (tid < 32) {
        float v = (tid < 4) ? red[tid] : -1e30f;
#pragma unroll
        for (int o = 2; o; o >>= 1) v = fmaxf(v, __shfl_xor_sync(~0u, v, o));
        if (tid == 0) red[0] = v;
    }
    __syncthreads();
    m = red[0];
    __syncthreads();

    // exp + sum
    float ssum = 0.0f;
    for (int i = tid; i < nk; i += 128) {
        float e = __expf(sc[i] - m);
        sc[i] = e;
        ssum += e;
    }
#pragma unroll
    for (int o = 16; o; o >>= 1) ssum += __shfl_xor_sync(~0u, ssum, o);
    if (lane == 0) red[warp] = ssum;
    __syncthreads();
    if (tid < 32) {
        float v = (tid < 4) ? red[tid] : 0.0f;
#pragma unroll
        for (int o = 2; o; o >>= 1) v += __shfl_xor_sync(~0u, v, o);
        if (tid == 0) red[0] = v;
    }
    __syncthreads();
    const float inv = 1.0f / red[0];

    // PV: thread tid owns output dim tid
    const float* vbase = g_qkv + 2 * H_DIM + h * HDIM + tid;
    float acc = 0.0f;
    int kk = 0;
    for (; kk + 4 <= nk; kk += 4) {
        float p0 = sc[kk], p1 = sc[kk + 1], p2 = sc[kk + 2], p3 = sc[kk + 3];
        acc += p0 * vbase[(size_t)(kk + 0) * QKV_N];
        acc += p1 * vbase[(size_t)(kk + 1) * QKV_N];
        acc += p2 * vbase[(size_t)(kk + 2) * QKV_N];
        acc += p3 * vbase[(size_t)(kk + 3) * QKV_N];
    }
    for (; kk < nk; kk++) acc += sc[kk] * vbase[(size_t)kk * QKV_N];

    g_attn[(size_t)t * H_DIM + h * HDIM + tid] = acc * inv;
}

// ---------------------------------------------------------------------------
extern "C" void kernel_launch(void* const* d_in, const int* in_sizes, int n_in,
                              void* d_out, int out_size) {
    const int* positions = (const int*)d_in[0];
    const float* hidden = (const float*)d_in[1];
    const float* w_qkv = (const float*)d_in[2];
    const float* q_norm_w = (const float*)d_in[3];
    const float* k_norm_w = (const float*)d_in[4];
    const float* w_o = (const float*)d_in[5];
    float* out = (float*)d_out;

    void* p_qkv = nullptr;
    void* p_attn = nullptr;
    cudaGetSymbolAddress(&p_qkv, g_qkv);
    cudaGetSymbolAddress(&p_attn, g_attn);

    // 1) QKV projection: [T, H] @ [H, 3H]
    {
        dim3 grid(QKV_N / 64, T_DIM / 64), block(16, 16);
        sgemm64<<<grid, block>>>(hidden, w_qkv, (float*)p_qkv, T_DIM, QKV_N, H_DIM);
    }
    // 2) RMSNorm + RoPE in-place on q,k
    rmsnorm_rope_kernel<<<T_DIM, 256>>>(positions, q_norm_w, k_norm_w);
    // 3) Causal attention
    {
        dim3 grid(T_DIM, NHEAD);
        attn_kernel<<<grid, 128>>>();
    }
    // 4) Output projection: [T, H] @ [H, H]
    {
        dim3 grid(H_DIM / 64, T_DIM / 64), block(16, 16);
        sgemm64<<<grid, block>>>((const float*)p_attn, w_o, out, T_DIM, H_DIM, H_DIM);
    }
}

// round 3
// speedup vs baseline: 1.7081x; 1.7081x over previous
#include <cuda_runtime.h>

#define T_DIM 2048
#define H_DIM 2048
#define NHEAD 16
#define HDIM 128
#define QKV_N (3 * H_DIM)
#define EPS_V 1e-6f
#define SCALE_V 0.08838834764831845f   // 128^-0.5
#define LOG_THETA 13.122363377404328f  // ln(500000)

// Scratch (device globals — no runtime allocation allowed)
__device__ float g_qkv[(size_t)T_DIM * QKV_N];   // 48 MB: [q | k | v] per row
__device__ float g_attn[(size_t)T_DIM * H_DIM];  // 16 MB

// ---------------------------------------------------------------------------
// SGEMM: C[M,N] = A[M,K] @ B[K,N], row-major. 128x128 tile, BK=16,
// 256 threads, 8x8 per thread (split 4+4 to keep LDS.128 conflict-free).
// Requires M%128==0, N%128==0, K%16==0.
// ---------------------------------------------------------------------------
__global__ void sgemm128(const float* __restrict__ A, const float* __restrict__ B,
                         float* __restrict__ C, int M, int N, int K) {
    __shared__ float As[16][132];  // [k][m]
    __shared__ float Bs[16][132];  // [k][n]

    const int tid = threadIdx.x;
    const int tx = tid & 15;       // col group
    const int ty = tid >> 4;       // row group
    const int row0 = blockIdx.y * 128;
    const int col0 = blockIdx.x * 128;

    const int am = tid >> 2;           // 0..63
    const int ak = (tid & 3) * 4;      // 0,4,8,12
    const int bk = tid >> 5;           // 0..7
    const int bn = (tid & 31) * 4;     // 0..124

    float acc[8][8];
#pragma unroll
    for (int i = 0; i < 8; i++)
#pragma unroll
        for (int j = 0; j < 8; j++) acc[i][j] = 0.0f;

    for (int k0 = 0; k0 < K; k0 += 16) {
        float4 a0 = *(const float4*)(A + (size_t)(row0 + am) * K + k0 + ak);
        float4 a1 = *(const float4*)(A + (size_t)(row0 + am + 64) * K + k0 + ak);
        As[ak + 0][am] = a0.x; As[ak + 1][am] = a0.y;
        As[ak + 2][am] = a0.z; As[ak + 3][am] = a0.w;
        As[ak + 0][am + 64] = a1.x; As[ak + 1][am + 64] = a1.y;
        As[ak + 2][am + 64] = a1.z; As[ak + 3][am + 64] = a1.w;

        float4 b0 = *(const float4*)(B + (size_t)(k0 + bk) * N + col0 + bn);
        float4 b1 = *(const float4*)(B + (size_t)(k0 + bk + 8) * N + col0 + bn);
        *(float4*)&Bs[bk][bn] = b0;
        *(float4*)&Bs[bk + 8][bn] = b1;
        __syncthreads();

#pragma unroll
        for (int kk = 0; kk < 16; kk++) {
            float a[8], b[8];
            *(float4*)&a[0] = *(float4*)&As[kk][ty * 4];
            *(float4*)&a[4] = *(float4*)&As[kk][ty * 4 + 64];
            *(float4*)&b[0] = *(float4*)&Bs[kk][tx * 4];
            *(float4*)&b[4] = *(float4*)&Bs[kk][tx * 4 + 64];
#pragma unroll
            for (int i = 0; i < 8; i++)
#pragma unroll
                for (int j = 0; j < 8; j++) acc[i][j] += a[i] * b[j];
        }
        __syncthreads();
    }

#pragma unroll
    for (int i = 0; i < 8; i++) {
        int r = row0 + ty * 4 + ((i < 4) ? i : (60 + i));  // ty*4 + i  or  ty*4+64+(i-4)
        float4 v0 = make_float4(acc[i][0], acc[i][1], acc[i][2], acc[i][3]);
        float4 v1 = make_float4(acc[i][4], acc[i][5], acc[i][6], acc[i][7]);
        *(float4*)(C + (size_t)r * N + col0 + tx * 4) = v0;
        *(float4*)(C + (size_t)r * N + col0 + tx * 4 + 64) = v1;
    }
}

// ---------------------------------------------------------------------------
// Fused RMSNorm (over full H=2048 for q and k) + RoPE, in-place on g_qkv.
// ---------------------------------------------------------------------------
__global__ void rmsnorm_rope_kernel(const int* __restrict__ positions,
                                    const float* __restrict__ qw,
                                    const float* __restrict__ kw) {
    const int t = blockIdx.x;
    float* q = g_qkv + (size_t)t * QKV_N;
    float* k = q + H_DIM;

    __shared__ float sh[32];
    const int lane = threadIdx.x & 31, warp = threadIdx.x >> 5;

    float sq = 0.0f, sk = 0.0f;
    for (int i = threadIdx.x; i < H_DIM; i += 256) {
        float a = q[i]; sq += a * a;
        float b = k[i]; sk += b * b;
    }
#pragma unroll
    for (int o = 16; o; o >>= 1) sq += __shfl_xor_sync(~0u, sq, o);
    if (lane == 0) sh[warp] = sq;
    __syncthreads();
    if (threadIdx.x < 32) {
        float v = (threadIdx.x < 8) ? sh[threadIdx.x] : 0.0f;
#pragma unroll
        for (int o = 4; o; o >>= 1) v += __shfl_xor_sync(~0u, v, o);
        if (threadIdx.x == 0) sh[0] = v;
    }
    __syncthreads();
    const float invq = rsqrtf(sh[0] / (float)H_DIM + EPS_V);
    __syncthreads();
#pragma unroll
    for (int o = 16; o; o >>= 1) sk += __shfl_xor_sync(~0u, sk, o);
    if (lane == 0) sh[warp] = sk;
    __syncthreads();
    if (threadIdx.x < 32) {
        float v = (threadIdx.x < 8) ? sh[threadIdx.x] : 0.0f;
#pragma unroll
        for (int o = 4; o; o >>= 1) v += __shfl_xor_sync(~0u, v, o);
        if (threadIdx.x == 0) sh[0] = v;
    }
    __syncthreads();
    const float invk = rsqrtf(sh[0] / (float)H_DIM + EPS_V);
    __syncthreads();

    const float p = (float)positions[t];
    for (int idx = threadIdx.x; idx < NHEAD * (HDIM / 2); idx += 256) {
        const int h = idx >> 6;
        const int d = idx & 63;
        const int i1 = h * HDIM + d;
        const int i2 = i1 + (HDIM / 2);
        const float fr = p * __expf(-LOG_THETA * (float)d * (1.0f / 64.0f));
        float c, s;
        __sincosf(fr, &s, &c);

        float q1 = q[i1] * invq * qw[i1];
        float q2 = q[i2] * invq * qw[i2];
        q[i1] = q1 * c - q2 * s;
        q[i2] = q2 * c + q1 * s;

        float k1 = k[i1] * invk * kw[i1];
        float k2 = k[i2] * invk * kw[i2];
        k[i1] = k1 * c - k2 * s;
        k[i2] = k2 * c + k1 * s;
    }
}

// ---------------------------------------------------------------------------
// Flash attention (fp32): one block per (head, 64-q-row tile). 256 threads,
// 8 warps. Warp w owns q rows w*8..w*8+7. Lane owns keys {lane, lane+32} of
// each 64-key tile and output dims lane*4..lane*4+3. Online softmax.
// ---------------------------------------------------------------------------
#define QT 64
#define KT 64
#define KPAD (HDIM + 4)
// smem (floats): Qs[QT][HDIM] | Ks[KT][KPAD] | Vs[KT][HDIM] | Ps[QT][KT]
#define SM_QS 0
#define SM_KS (SM_QS + QT * HDIM)
#define SM_VS (SM_KS + KT * KPAD)
#define SM_PS (SM_VS + KT * HDIM)
#define SM_FLOATS (SM_PS + QT * KT)
#define SM_BYTES (SM_FLOATS * 4)

__global__ void flash_attn() {
    extern __shared__ float sm[];
    float* Qs = sm + SM_QS;
    float* Ks = sm + SM_KS;
    float* Vs = sm + SM_VS;
    float* Ps = sm + SM_PS;

    const int h = blockIdx.y;
    const int qt = gridDim.x - 1 - blockIdx.x;  // heavy tiles scheduled first
    const int q0 = qt * QT;
    const int tid = threadIdx.x;
    const int warp = tid >> 5, lane = tid & 31;

    // Load Q tile (pre-scaled)
    for (int i = tid; i < QT * (HDIM / 4); i += 256) {
        int q = i >> 5;
        int d4 = (i & 31) * 4;
        float4 v = *(const float4*)(g_qkv + (size_t)(q0 + q) * QKV_N + h * HDIM + d4);
        v.x *= SCALE_V; v.y *= SCALE_V; v.z *= SCALE_V; v.w *= SCALE_V;
        *(float4*)&Qs[q * HDIM + d4] = v;
    }

    float m[8], l[8], acc[8][4];
#pragma unroll
    for (int i = 0; i < 8; i++) {
        m[i] = -1e30f; l[i] = 0.0f;
#pragma unroll
        for (int j = 0; j < 4; j++) acc[i][j] = 0.0f;
    }

    const int ntiles = qt + 1;
    for (int t = 0; t < ntiles; t++) {
        const int k0 = t * KT;
        __syncthreads();  // previous PV done (and Qs load on t==0)
        // Load K and V tiles
        for (int i = tid; i < KT * (HDIM / 4); i += 256) {
            int k = i >> 5;
            int d4 = (i & 31) * 4;
            const float* base = g_qkv + (size_t)(k0 + k) * QKV_N + h * HDIM + d4;
            *(float4*)&Ks[k * KPAD + d4] = *(const float4*)(base + H_DIM);
            *(float4*)&Vs[k * HDIM + d4] = *(const float4*)(base + 2 * H_DIM);
        }
        __syncthreads();

        // Scores: s[qi][0] = q·K[lane], s[qi][1] = q·K[lane+32]
        float s[8][2];
#pragma unroll
        for (int qi = 0; qi < 8; qi++) { s[qi][0] = 0.0f; s[qi][1] = 0.0f; }

        const float* k0p = Ks + lane * KPAD;
        const float* k1p = Ks + (lane + 32) * KPAD;
#pragma unroll 4
        for (int d = 0; d < HDIM; d += 4) {
            float4 ka = *(const float4*)(k0p + d);
            float4 kb = *(const float4*)(k1p + d);
#pragma unroll
            for (int qi = 0; qi < 8; qi++) {
                float4 qv = *(const float4*)&Qs[(warp * 8 + qi) * HDIM + d];
                s[qi][0] += qv.x * ka.x + qv.y * ka.y + qv.z * ka.z + qv.w * ka.w;
                s[qi][1] += qv.x * kb.x + qv.y * kb.y + qv.z * kb.z + qv.w * kb.w;
            }
        }

        // Causal mask on the diagonal tile (positions are arange)
        if (t == qt) {
#pragma unroll
            for (int qi = 0; qi < 8; qi++) {
                int qloc = warp * 8 + qi;
                if (lane > qloc) s[qi][0] = -1e30f;
                if (lane + 32 > qloc) s[qi][1] = -1e30f;
            }
        }

        // Online softmax + write P
#pragma unroll
        for (int qi = 0; qi < 8; qi++) {
            float mt = fmaxf(s[qi][0], s[qi][1]);
#pragma unroll
            for (int o = 16; o; o >>= 1) mt = fmaxf(mt, __shfl_xor_sync(~0u, mt, o));
            float mnew = fmaxf(m[qi], mt);
            float corr = __expf(m[qi] - mnew);
            float p0 = __expf(s[qi][0] - mnew);
            float p1 = __expf(s[qi][1] - mnew);
            float ps = p0 + p1;
#pragma unroll
            for (int o = 16; o; o >>= 1) ps += __shfl_xor_sync(~0u, ps, o);
            l[qi] = l[qi] * corr + ps;
            m[qi] = mnew;
#pragma unroll
            for (int j = 0; j < 4; j++) acc[qi][j] *= corr;
            Ps[(warp * 8 + qi) * KT + lane] = p0;
            Ps[(warp * 8 + qi) * KT + lane + 32] = p1;
        }
        __syncwarp();

        // PV: acc[qi][:] += P[qi][kk] * V[kk][lane*4..]
#pragma unroll 4
        for (int kk = 0; kk < KT; kk += 2) {
            float4 v0 = *(const float4*)&Vs[kk * HDIM + lane * 4];
            float4 v1 = *(const float4*)&Vs[(kk + 1) * HDIM + lane * 4];
#pragma unroll
            for (int qi = 0; qi < 8; qi++) {
                float2 p = *(const float2*)&Ps[(warp * 8 + qi) * KT + kk];
                acc[qi][0] += p.x * v0.x + p.y * v1.x;
                acc[qi][1] += p.x * v0.y + p.y * v1.y;
                acc[qi][2] += p.x * v0.z + p.y * v1.z;
                acc[qi][3] += p.x * v0.w + p.y * v1.w;
            }
        }
    }

    // Write output
#pragma unroll
    for (int qi = 0; qi < 8; qi++) {
        float inv = 1.0f / l[qi];
        float4 o = make_float4(acc[qi][0] * inv, acc[qi][1] * inv,
                               acc[qi][2] * inv, acc[qi][3] * inv);
        *(float4*)(g_attn + (size_t)(q0 + warp * 8 + qi) * H_DIM + h * HDIM + lane * 4) = o;
    }
}

// ---------------------------------------------------------------------------
extern "C" void kernel_launch(void* const* d_in, const int* in_sizes, int n_in,
                              void* d_out, int out_size) {
    const int* positions = (const int*)d_in[0];
    const float* hidden = (const float*)d_in[1];
    const float* w_qkv = (const float*)d_in[2];
    const float* q_norm_w = (const float*)d_in[3];
    const float* k_norm_w = (const float*)d_in[4];
    const float* w_o = (const float*)d_in[5];
    float* out = (float*)d_out;

    void* p_qkv = nullptr;
    void* p_attn = nullptr;
    cudaGetSymbolAddress(&p_qkv, g_qkv);
    cudaGetSymbolAddress(&p_attn, g_attn);

    cudaFuncSetAttribute(flash_attn, cudaFuncAttributeMaxDynamicSharedMemorySize, SM_BYTES);

    // 1) QKV projection: [T, H] @ [H, 3H]
    {
        dim3 grid(QKV_N / 128, T_DIM / 128), block(256);
        sgemm128<<<grid, block>>>(hidden, w_qkv, (float*)p_qkv, T_DIM, QKV_N, H_DIM);
    }
    // 2) RMSNorm + RoPE in-place on q,k
    rmsnorm_rope_kernel<<<T_DIM, 256>>>(positions, q_norm_w, k_norm_w);
    // 3) Causal flash attention
    {
        dim3 grid(T_DIM / QT, NHEAD);
        flash_attn<<<grid, 256, SM_BYTES>>>();
    }
    // 4) Output projection: [T, H] @ [H, H]
    {
        dim3 grid(H_DIM / 128, T_DIM / 128), block(256);
        sgemm128<<<grid, block>>>((const float*)p_attn, w_o, out, T_DIM, H_DIM, H_DIM);
    }
}